// round 3
// baseline (speedup 1.0000x reference)
#include <cuda_runtime.h>
#include <math.h>

// Problem constants (shapes fixed by setup_inputs)
#define C_DIM   20
#define HW      524288      // 512*1024
#define HW2     262144      // HW/2  (float2 units)
#define HW2_SH  18          // log2(HW2)
#define BLK     256

// Prep output: duplicated normalized prototypes (p,p) + per-row squared norms
__device__ float2 g_proto2[C_DIM * C_DIM];
__device__ float  g_psqn[C_DIM];

__device__ __forceinline__ float sqrt_approx(float v) {
    float r; asm("sqrt.approx.f32 %0, %1;" : "=f"(r) : "f"(v)); return r;
}
__device__ __forceinline__ float rcp_approx(float v) {
    float r; asm("rcp.approx.f32 %0, %1;" : "=f"(r) : "f"(v)); return r;
}
// packed fp32x2 FMA: d = a*b + d   (FFMA2 — only reachable via PTX)
__device__ __forceinline__ void ffma2(unsigned long long& d,
                                      unsigned long long a,
                                      unsigned long long b) {
    asm("fma.rn.f32x2 %0, %1, %2, %0;" : "+l"(d) : "l"(a), "l"(b));
}
__device__ __forceinline__ unsigned long long pack2(float lo, float hi) {
    unsigned long long r;
    asm("mov.b64 %0, {%1, %2};" : "=l"(r) : "f"(lo), "f"(hi));
    return r;
}
__device__ __forceinline__ void unpack2(float& lo, float& hi, unsigned long long v) {
    asm("mov.b64 {%0, %1}, %2;" : "=f"(lo), "=f"(hi) : "l"(v));
}

// ---------------------------------------------------------------------------
// Prep: normalize prototype rows, store duplicated (p,p) rows + squared norms.
// ---------------------------------------------------------------------------
__global__ void proto_prep_kernel(const float* __restrict__ protos) {
    int m = threadIdx.x;
    if (m < C_DIM) {
        float v[C_DIM];
        float sq = 0.f;
        #pragma unroll
        for (int c = 0; c < C_DIM; c++) {
            v[c] = protos[m * C_DIM + c];
            sq = fmaf(v[c], v[c], sq);
        }
        float inv = 1.0f / fmaxf(sqrtf(sq), 1e-12f);
        float s = 0.f;
        #pragma unroll
        for (int c = 0; c < C_DIM; c++) {
            float pv = v[c] * inv;
            g_proto2[m * C_DIM + c] = make_float2(pv, pv);
            s = fmaf(pv, pv, s);
        }
        g_psqn[m] = s;
    }
}

// ---------------------------------------------------------------------------
// Main kernel: each thread owns 2 consecutive pixels (one float2 along W),
// packed into 64-bit register pairs; all math on the pair via fma.rn.f32x2.
//   input  float2 idx: b*C*HW2 + c*HW2 + rem
//   output float2 idx: b*C*HW2 + m*HW2 + rem
// ---------------------------------------------------------------------------
__global__ __launch_bounds__(BLK, 4)
void isomax_dist_kernel(const float* __restrict__ in,
                        const float* __restrict__ scale_p,
                        float* __restrict__ out) {
    __shared__ float2 sp2[C_DIM * C_DIM];   // duplicated normalized protos
    __shared__ float  spsn[C_DIM];
    for (int i = threadIdx.x; i < C_DIM * C_DIM; i += BLK)
        sp2[i] = g_proto2[i];
    if (threadIdx.x < C_DIM)
        spsn[threadIdx.x] = g_psqn[threadIdx.x];
    __syncthreads();

    const float sneg = -fabsf(__ldg(scale_p));   // logits = -|scale| * dist

    const float2* __restrict__ in2  = (const float2*)in;
    float2*       __restrict__ out2 = (float2*)out;

    unsigned q   = blockIdx.x * BLK + threadIdx.x;   // global pixel-pair index
    unsigned b   = q >> HW2_SH;
    unsigned rem = q & (HW2 - 1u);
    unsigned base2 = b * (C_DIM * HW2) + rem;

    // Load the 20-channel pair-vectors (20 x LDG.64, coalesced, deep MLP)
    unsigned long long x2[C_DIM];
    #pragma unroll
    for (int c = 0; c < C_DIM; c++) {
        float2 v = in2[base2 + (unsigned)c * HW2];
        x2[c] = pack2(v.x, v.y);
    }

    // Squared norms per pixel (packed)
    unsigned long long xsq2 = 0ull;
    #pragma unroll
    for (int c = 0; c < C_DIM; c++)
        ffma2(xsq2, x2[c], x2[c]);
    float xsqx, xsqy;
    unpack2(xsqx, xsqy, xsq2);

    float invx = rcp_approx(fmaxf(sqrt_approx(xsqx), 1e-12f));
    float invy = rcp_approx(fmaxf(sqrt_approx(xsqy), 1e-12f));
    float xnx = xsqx * invx * invx;    // ||x_hat||^2
    float xny = xsqy * invy * invy;
    float n2ix = -2.f * invx;
    float n2iy = -2.f * invy;

    const unsigned long long* spu = (const unsigned long long*)sp2;

    #pragma unroll 1
    for (int m = 0; m < C_DIM; m++) {
        const unsigned long long* pr = spu + m * C_DIM;
        unsigned long long dot2 = 0ull;
        #pragma unroll
        for (int c = 0; c < C_DIM; c++)
            ffma2(dot2, x2[c], pr[c]);   // LDS.64 broadcast + FFMA2

        float dx, dy;
        unpack2(dx, dy, dot2);
        float psn = spsn[m];
        float d2x = fmaf(dx, n2ix, xnx + psn);
        float d2y = fmaf(dy, n2iy, xny + psn);
        d2x = fmaxf(d2x, 0.f);
        d2y = fmaxf(d2y, 0.f);

        float2 o;
        o.x = sneg * sqrt_approx(d2x);
        o.y = sneg * sqrt_approx(d2y);
        out2[base2 + (unsigned)m * HW2] = o;
    }
}

extern "C" void kernel_launch(void* const* d_in, const int* in_sizes, int n_in,
                              void* d_out, int out_size) {
    const float* features = (const float*)d_in[0];  // [8,20,512,1024] f32
    const float* protos   = (const float*)d_in[1];  // [20,20] f32
    const float* dscale   = (const float*)d_in[2];  // [1] f32

    proto_prep_kernel<<<1, 32>>>(protos);

    int n_pix2 = (in_sizes[0] / C_DIM) / 2;         // pixel pairs
    int grid = (n_pix2 + BLK - 1) / BLK;
    isomax_dist_kernel<<<grid, BLK>>>(features, dscale, (float*)d_out);
}

// round 4
// speedup vs baseline: 1.1935x; 1.1935x over previous
#include <cuda_runtime.h>
#include <math.h>

// Problem constants (shapes fixed by setup_inputs)
#define C_DIM   20
#define C2      10          // channel pairs
#define HW      524288      // 512*1024
#define HW4     131072      // HW/4 (float4 units)
#define HW4_SH  17          // log2(HW4)
#define BLK     256

// Prep output: normalized prototypes [m][c] (natural layout => pair-adjacent)
// + per-row squared norms
__device__ float g_proto[C_DIM * C_DIM];
__device__ float g_psqn[C_DIM];

__device__ __forceinline__ float sqrt_approx(float v) {
    float r; asm("sqrt.approx.f32 %0, %1;" : "=f"(r) : "f"(v)); return r;
}
__device__ __forceinline__ float rsqrt_approx(float v) {
    float r; asm("rsqrt.approx.f32 %0, %1;" : "=f"(r) : "f"(v)); return r;
}
// packed fp32x2 FMA: d = a*b + d   (FFMA2 — only reachable via PTX)
__device__ __forceinline__ void ffma2(unsigned long long& d,
                                      unsigned long long a,
                                      unsigned long long b) {
    asm("fma.rn.f32x2 %0, %1, %2, %0;" : "+l"(d) : "l"(a), "l"(b));
}
__device__ __forceinline__ unsigned long long pack2(float lo, float hi) {
    unsigned long long r;
    asm("mov.b64 %0, {%1, %2};" : "=l"(r) : "f"(lo), "f"(hi));
    return r;
}
__device__ __forceinline__ void unpack2(float& lo, float& hi, unsigned long long v) {
    asm("mov.b64 {%0, %1}, %2;" : "=f"(lo), "=f"(hi) : "l"(v));
}

// ---------------------------------------------------------------------------
// Prep: normalize prototype rows (dim=1), store rows + squared norms.
// ---------------------------------------------------------------------------
__global__ void proto_prep_kernel(const float* __restrict__ protos) {
    int m = threadIdx.x;
    if (m < C_DIM) {
        float v[C_DIM];
        float sq = 0.f;
        #pragma unroll
        for (int c = 0; c < C_DIM; c++) {
            v[c] = protos[m * C_DIM + c];
            sq = fmaf(v[c], v[c], sq);
        }
        float inv = 1.0f / fmaxf(sqrtf(sq), 1e-12f);
        float s = 0.f;
        #pragma unroll
        for (int c = 0; c < C_DIM; c++) {
            float pv = v[c] * inv;
            g_proto[m * C_DIM + c] = pv;
            s = fmaf(pv, pv, s);
        }
        g_psqn[m] = s;
    }
}

// ---------------------------------------------------------------------------
// Main kernel: 4 consecutive pixels per thread (one float4 along W).
// Channel-pair packing: x pairs (x_{2c}, x_{2c+1}) per pixel in 64-bit regs;
// dot product via fma.rn.f32x2 against prototype channel-pairs from smem
// (LDS.128 delivers two pairs). Horizontal lo+hi add finishes each dot.
//   input  float4 idx: b*C*HW4 + c*HW4 + rem
//   output float4 idx: b*C*HW4 + m*HW4 + rem
// ---------------------------------------------------------------------------
__global__ __launch_bounds__(BLK, 2)
void isomax_dist_kernel(const float* __restrict__ in,
                        const float* __restrict__ scale_p,
                        float* __restrict__ out) {
    __shared__ float sp[C_DIM * C_DIM];   // rows of 20 floats = 10 pairs (80B, 16B-aligned)
    __shared__ float spsn[C_DIM];
    for (int i = threadIdx.x; i < C_DIM * C_DIM; i += BLK)
        sp[i] = g_proto[i];
    if (threadIdx.x < C_DIM)
        spsn[threadIdx.x] = g_psqn[threadIdx.x];
    __syncthreads();

    const float sneg = -fabsf(__ldg(scale_p));   // logits = -|scale| * dist

    const float4* __restrict__ in4  = (const float4*)in;
    float4*       __restrict__ out4 = (float4*)out;

    unsigned q   = blockIdx.x * BLK + threadIdx.x;   // global float4-pixel index
    unsigned b   = q >> HW4_SH;
    unsigned rem = q & (HW4 - 1u);
    unsigned base4 = b * (C_DIM * HW4) + rem;

    // Load 20 channels for 4 pixels; pack along channel pairs:
    //   xp[c2*4 + j] = (x_{2c2}[j], x_{2c2+1}[j])
    // Also fold the squared-norm accumulation into the pack phase.
    unsigned long long xp[C2 * 4];
    unsigned long long xsq2[4] = {0ull, 0ull, 0ull, 0ull};
    #pragma unroll
    for (int c2 = 0; c2 < C2; c2++) {
        float4 a  = in4[base4 + (unsigned)(2 * c2)     * HW4];
        float4 b4 = in4[base4 + (unsigned)(2 * c2 + 1) * HW4];
        unsigned long long p0 = pack2(a.x, b4.x);
        unsigned long long p1 = pack2(a.y, b4.y);
        unsigned long long p2 = pack2(a.z, b4.z);
        unsigned long long p3 = pack2(a.w, b4.w);
        xp[c2 * 4 + 0] = p0; ffma2(xsq2[0], p0, p0);
        xp[c2 * 4 + 1] = p1; ffma2(xsq2[1], p1, p1);
        xp[c2 * 4 + 2] = p2; ffma2(xsq2[2], p2, p2);
        xp[c2 * 4 + 3] = p3; ffma2(xsq2[3], p3, p3);
    }

    // Per-pixel: inv = 1/||x|| (rsqrt, clamped), xn = ||x_hat||^2, n2i = -2*inv
    float xn[4], n2i[4];
    #pragma unroll
    for (int j = 0; j < 4; j++) {
        float lo, hi;
        unpack2(lo, hi, xsq2[j]);
        float xsq = lo + hi;
        float inv = rsqrt_approx(fmaxf(xsq, 1e-24f));
        xn[j]  = xsq * inv * inv;
        n2i[j] = -2.f * inv;
    }

    #pragma unroll 1
    for (int m = 0; m < C_DIM; m++) {
        // prototype row m as 5 x ulonglong2 (each = 2 channel pairs), LDS.128
        const ulonglong2* pr = (const ulonglong2*)&sp[m * C_DIM];
        unsigned long long acc[4] = {0ull, 0ull, 0ull, 0ull};
        #pragma unroll
        for (int c4 = 0; c4 < C2 / 2; c4++) {
            ulonglong2 pp = pr[c4];
            ffma2(acc[0], xp[(2 * c4) * 4 + 0], pp.x);
            ffma2(acc[1], xp[(2 * c4) * 4 + 1], pp.x);
            ffma2(acc[2], xp[(2 * c4) * 4 + 2], pp.x);
            ffma2(acc[3], xp[(2 * c4) * 4 + 3], pp.x);
            ffma2(acc[0], xp[(2 * c4 + 1) * 4 + 0], pp.y);
            ffma2(acc[1], xp[(2 * c4 + 1) * 4 + 1], pp.y);
            ffma2(acc[2], xp[(2 * c4 + 1) * 4 + 2], pp.y);
            ffma2(acc[3], xp[(2 * c4 + 1) * 4 + 3], pp.y);
        }
        float psn = spsn[m];

        float4 o;
        #pragma unroll
        for (int j = 0; j < 4; j++) {
            float lo, hi;
            unpack2(lo, hi, acc[j]);
            float dot = lo + hi;
            float d2 = fmaf(dot, n2i[j], xn[j] + psn);
            d2 = fmaxf(d2, 0.f);
            ((float*)&o)[j] = sneg * sqrt_approx(d2);
        }
        out4[base4 + (unsigned)m * HW4] = o;
    }
}

extern "C" void kernel_launch(void* const* d_in, const int* in_sizes, int n_in,
                              void* d_out, int out_size) {
    const float* features = (const float*)d_in[0];  // [8,20,512,1024] f32
    const float* protos   = (const float*)d_in[1];  // [20,20] f32
    const float* dscale   = (const float*)d_in[2];  // [1] f32

    proto_prep_kernel<<<1, 32>>>(protos);

    int n_pix4 = (in_sizes[0] / C_DIM) / 4;         // float4 pixel groups
    int grid = (n_pix4 + BLK - 1) / BLK;
    isomax_dist_kernel<<<grid, BLK>>>(features, dscale, (float*)d_out);
}